// round 1
// baseline (speedup 1.0000x reference)
#include <cuda_runtime.h>
#include <cstdint>
#include <cstddef>

#define BSZ  16384
#define SDIM 1024
#define ADIM 64
#define HID  1024
#define REC  1024
#define LATD 1024

// Scratch (static device allocations are the allowed mechanism)
__device__ float g_x [(size_t)BSZ * HID];        //  64 MB
__device__ float g_gi[(size_t)BSZ * 3 * REC];    // 201 MB
__device__ float g_gh[(size_t)BSZ * 3 * REC];    // 201 MB

// ---------------- fp32 tiled GEMM ----------------
// C[m,n] = bias[n] + sum_k Acat[m,k] * B[n,k]
// Acat = [A1 (optionally masked per-row) | A2], both row-major K-contiguous.
// B is N x (K1+K2) row-major (i.e. we compute X @ B^T).
#define GBM 128
#define GBN 128
#define GBK 16
#define GTM 8
#define GTN 8

__global__ __launch_bounds__(256, 2)
void gemm_kernel(const float* __restrict__ A1, int K1,
                 const float* __restrict__ A2, int K2,
                 const unsigned char* __restrict__ mask,
                 const float* __restrict__ B,
                 const float* __restrict__ bias,
                 float* __restrict__ C, int N)
{
    __shared__ __align__(16) float As[GBK][GBM];
    __shared__ __align__(16) float Bs[GBK][GBN];
    const int K  = K1 + K2;
    const int bm = blockIdx.y * GBM;
    const int bn = blockIdx.x * GBN;
    const int t  = threadIdx.x;
    const int tx = t & 15;   // n direction
    const int ty = t >> 4;   // m direction

    float acc[GTM][GTN];
#pragma unroll
    for (int i = 0; i < GTM; i++)
#pragma unroll
        for (int j = 0; j < GTN; j++) acc[i][j] = 0.f;

    for (int kt = 0; kt < K; kt += GBK) {
#pragma unroll
        for (int q = 0; q < 2; q++) {
            int li  = t * 2 + q;       // 0..511
            int row = li >> 2;         // 0..127
            int kq  = (li & 3) << 2;   // 0,4,8,12
            int kg  = kt + kq;
            // A tile (concat + mask); float4 never straddles K1 (K1 % 4 == 0)
            {
                int m = bm + row;
                float4 v;
                if (kg < K1) {
                    if (mask != nullptr && mask[m]) v = make_float4(0.f, 0.f, 0.f, 0.f);
                    else v = *reinterpret_cast<const float4*>(A1 + (size_t)m * K1 + kg);
                } else {
                    v = *reinterpret_cast<const float4*>(A2 + (size_t)m * K2 + (kg - K1));
                }
                As[kq + 0][row] = v.x; As[kq + 1][row] = v.y;
                As[kq + 2][row] = v.z; As[kq + 3][row] = v.w;
            }
            // B tile
            {
                int n = bn + row;
                float4 w = *reinterpret_cast<const float4*>(B + (size_t)n * K + kg);
                Bs[kq + 0][row] = w.x; Bs[kq + 1][row] = w.y;
                Bs[kq + 2][row] = w.z; Bs[kq + 3][row] = w.w;
            }
        }
        __syncthreads();
#pragma unroll
        for (int k = 0; k < GBK; k++) {
            float4 a0 = *reinterpret_cast<const float4*>(&As[k][ty * GTM]);
            float4 a1 = *reinterpret_cast<const float4*>(&As[k][ty * GTM + 4]);
            float4 b0 = *reinterpret_cast<const float4*>(&Bs[k][tx * GTN]);
            float4 b1 = *reinterpret_cast<const float4*>(&Bs[k][tx * GTN + 4]);
            float a[8] = {a0.x, a0.y, a0.z, a0.w, a1.x, a1.y, a1.z, a1.w};
            float b[8] = {b0.x, b0.y, b0.z, b0.w, b1.x, b1.y, b1.z, b1.w};
#pragma unroll
            for (int i = 0; i < GTM; i++)
#pragma unroll
                for (int j = 0; j < GTN; j++)
                    acc[i][j] = fmaf(a[i], b[j], acc[i][j]);
        }
        __syncthreads();
    }
#pragma unroll
    for (int i = 0; i < GTM; i++) {
        int m = bm + ty * GTM + i;
        float* crow = C + (size_t)m * N + bn + tx * GTN;
#pragma unroll
        for (int j = 0; j < GTN; j++)
            crow[j] = acc[i][j] + bias[bn + tx * GTN + j];
    }
}

// ---------------- GRU elementwise combine ----------------
__global__ void gru_kernel(const float* __restrict__ deter,
                           const unsigned char* __restrict__ first,
                           float* __restrict__ h_out)
{
    int i = blockIdx.x * blockDim.x + threadIdx.x;
    if (i >= BSZ * REC) return;
    int m = i >> 10;
    int n = i & 1023;
    size_t base = (size_t)m * (3 * REC) + n;
    float ir  = g_gi[base];
    float iz  = g_gi[base + REC];
    float i_n = g_gi[base + 2 * REC];
    float hr  = g_gh[base];
    float hz  = g_gh[base + REC];
    float h_n = g_gh[base + 2 * REC];
    float d = first[m] ? 0.f : deter[i];
    float r  = 1.f / (1.f + expf(-(ir + hr)));
    float z  = 1.f / (1.f + expf(-(iz + hz)));
    float nn = tanhf(i_n + r * h_n);
    h_out[i] = (1.f - z) * nn + z * d;
}

// ---------------- threefry2x32 (JAX partitionable path) ----------------
// key = jax.random.key(42) -> (k0, k1) = (0, 42). count is a uint64 flat index;
// here count < 2^32 so x0 = hi(count) = 0, x1 = lo(count) = idx.
// 32-bit random bits = out0 ^ out1.
__device__ __forceinline__ uint32_t threefry_bits(uint32_t x1in)
{
    const uint32_t ks0 = 0u;
    const uint32_t ks1 = 42u;
    const uint32_t ks2 = 0x1BD11BDAu ^ ks0 ^ ks1;
    uint32_t x0 = 0u + ks0;
    uint32_t x1 = x1in + ks1;
#define TF_R(r) { x0 += x1; x1 = __funnelshift_l(x1, x1, (r)); x1 ^= x0; }
    TF_R(13) TF_R(15) TF_R(26) TF_R(6)
    x0 += ks1; x1 += ks2 + 1u;
    TF_R(17) TF_R(29) TF_R(16) TF_R(24)
    x0 += ks2; x1 += ks0 + 2u;
    TF_R(13) TF_R(15) TF_R(26) TF_R(6)
    x0 += ks0; x1 += ks1 + 3u;
    TF_R(17) TF_R(29) TF_R(16) TF_R(24)
    x0 += ks1; x1 += ks2 + 4u;
    TF_R(13) TF_R(15) TF_R(26) TF_R(6)
    x0 += ks2; x1 += ks0 + 5u;
#undef TF_R
    return x0 ^ x1;
}

// One thread per (batch, group): 32 categories, gumbel-argmax, one-hot out.
__global__ void sample_kernel(const float* __restrict__ logits,
                              float* __restrict__ stoch_out)
{
    int g = blockIdx.x * blockDim.x + threadIdx.x;
    if (g >= BSZ * 32) return;
    const float4* lrow = reinterpret_cast<const float4*>(logits + (size_t)g * 32);
    float best = -3.4e38f;
    int   bi   = 0;
    uint32_t base = (uint32_t)g * 32u;
#pragma unroll
    for (int q = 0; q < 8; q++) {
        float4 lv = lrow[q];
        float l4[4] = {lv.x, lv.y, lv.z, lv.w};
#pragma unroll
        for (int c = 0; c < 4; c++) {
            int d = q * 4 + c;
            uint32_t bits = threefry_bits(base + (uint32_t)d);
            // jax uniform: f in [0,1) from top 23 bits; u = tiny iff f == 0
            float f = __uint_as_float((bits >> 9) | 0x3f800000u) - 1.0f;
            float u = fmaxf(f, 1.17549435e-38f);
            // inner log MUST be accurate (u near 1 -> result ~1e-7; __logf abs
            // error there is larger than the value and can flip sign -> NaN).
            float inner = -logf(u);
            float gmb   = -__logf(inner);   // outer: fast log is fine
            float s = l4[c] + gmb;
            if (s > best) { best = s; bi = d; }   // strict '>' = first-max tie rule
        }
    }
    float4* dst = reinterpret_cast<float4*>(stoch_out + (size_t)g * 32);
#pragma unroll
    for (int q = 0; q < 8; q++) {
        float4 v;
        v.x = (bi == q * 4 + 0) ? 1.f : 0.f;
        v.y = (bi == q * 4 + 1) ? 1.f : 0.f;
        v.z = (bi == q * 4 + 2) ? 1.f : 0.f;
        v.w = (bi == q * 4 + 3) ? 1.f : 0.f;
        dst[q] = v;
    }
}

// ---------------- launch ----------------
extern "C" void kernel_launch(void* const* d_in, const int* in_sizes, int n_in,
                              void* d_out, int out_size)
{
    (void)in_sizes; (void)n_in; (void)out_size;
    const float* stoch  = (const float*)d_in[0];
    const float* deter  = (const float*)d_in[1];
    // d_in[2] logits_prev: unused by reference
    const float* action = (const float*)d_in[3];
    const float* obs    = (const float*)d_in[4];
    const unsigned char* first = (const unsigned char*)d_in[5];
    const float* W_in   = (const float*)d_in[6];
    const float* b_in   = (const float*)d_in[7];
    const float* W_ih   = (const float*)d_in[8];
    const float* b_ih   = (const float*)d_in[9];
    const float* W_hh   = (const float*)d_in[10];
    const float* b_hh   = (const float*)d_in[11];
    // d_in[12..13] W_prior/b_prior: dead code in reference (result unused)
    const float* W_post = (const float*)d_in[14];
    const float* b_post = (const float*)d_in[15];

    float* out        = (float*)d_out;
    float* h_out      = out;                              // (BS, REC)
    float* stoch_out  = out + (size_t)BSZ * LATD;         // (BS, LAT)
    float* logits_out = out + 2 * (size_t)BSZ * LATD;     // (BS, LAT)

    float *xp, *gip, *ghp;
    cudaGetSymbolAddress((void**)&xp,  g_x);
    cudaGetSymbolAddress((void**)&gip, g_gi);
    cudaGetSymbolAddress((void**)&ghp, g_gh);

    dim3 thr(256);
    // x = [stoch*(~first), action] @ W_in^T + b_in          (K = 1088)
    gemm_kernel<<<dim3(HID / GBN, BSZ / GBM), thr>>>(
        stoch, SDIM, action, ADIM, first, W_in, b_in, xp, HID);
    // gi = x @ W_ih^T + b_ih                                (N = 3072)
    gemm_kernel<<<dim3(3 * REC / GBN, BSZ / GBM), thr>>>(
        xp, HID, nullptr, 0, nullptr, W_ih, b_ih, gip, 3 * REC);
    // gh = deter*(~first) @ W_hh^T + b_hh                   (N = 3072)
    gemm_kernel<<<dim3(3 * REC / GBN, BSZ / GBM), thr>>>(
        deter, REC, nullptr, 0, first, W_hh, b_hh, ghp, 3 * REC);
    // h (GRU combine) -> d_out region 0
    gru_kernel<<<(BSZ * REC) / 256, 256>>>(deter, first, h_out);
    // logits = [h, obs] @ W_post^T + b_post -> d_out region 2  (K = 2048)
    gemm_kernel<<<dim3(LATD / GBN, BSZ / GBM), thr>>>(
        h_out, REC, obs, HID, nullptr, W_post, b_post, logits_out, LATD);
    // gumbel-categorical one-hot sample -> d_out region 1
    sample_kernel<<<(BSZ * 32) / 256, 256>>>(logits_out, stoch_out);
}

// round 5
// speedup vs baseline: 1.1546x; 1.1546x over previous
#include <cuda_runtime.h>
#include <cstdint>
#include <cstddef>

#define BSZ  16384
#define SDIM 1024
#define ADIM 64
#define HID  1024
#define REC  1024
#define LATD 1024

// Scratch
__device__ float g_x [(size_t)BSZ * HID];
__device__ float g_gi[(size_t)BSZ * 3 * REC];
__device__ float g_gh[(size_t)BSZ * 3 * REC];

// Pre-split weights (hi/lo tf32): W_in | W_ih | W_hh | W_post
#define OFF_IN   0
#define SZ_IN    ((SDIM + ADIM) * HID)
#define OFF_IH   (OFF_IN + SZ_IN)
#define SZ_IH    (3 * REC * HID)
#define OFF_HH   (OFF_IH + SZ_IH)
#define SZ_HH    (3 * REC * REC)
#define OFF_POST (OFF_HH + SZ_HH)
#define SZ_POST  (LATD * (REC + HID))
#define W_TOTAL  (OFF_POST + SZ_POST)
__device__ float g_wh[(size_t)W_TOTAL];
__device__ float g_wl[(size_t)W_TOTAL];

// ---- ambiguous-group fix machinery ----
#define FIX_TAU  2e-4f
#define AMB_CAP  16384
#define FIX_ROWS 384
__device__ int   g_namb;
__device__ int   g_nrows;
__device__ int   g_amb[AMB_CAP];
__device__ int   g_rowlist[FIX_ROWS];
__device__ int   g_rowflag[BSZ];
__device__ float g_fin [(size_t)FIX_ROWS * 1088];
__device__ float g_fdet[(size_t)FIX_ROWS * 1024];
__device__ float g_fobs[(size_t)FIX_ROWS * 1024];
__device__ float g_fx  [(size_t)FIX_ROWS * 1024];
__device__ float g_fgi [(size_t)FIX_ROWS * 3072];
__device__ float g_fgh [(size_t)FIX_ROWS * 3072];
__device__ float g_fh  [(size_t)FIX_ROWS * 1024];
__device__ float g_flog[(size_t)FIX_ROWS * 1024];

__device__ __forceinline__ float tf32_rna(float a) {
    uint32_t u;
    asm("cvt.rna.tf32.f32 %0, %1;" : "=r"(u) : "f"(a));
    return __uint_as_float(u);
}

// ---------------- weight split kernel ----------------
__global__ void split_w_kernel(const float* __restrict__ W_in,
                               const float* __restrict__ W_ih,
                               const float* __restrict__ W_hh,
                               const float* __restrict__ W_post)
{
    int i4 = blockIdx.x * blockDim.x + threadIdx.x;
    size_t i = (size_t)i4 * 4;
    if (i >= W_TOTAL) return;
    const float* src;
    size_t off;
    if      (i < OFF_IH)   { src = W_in;   off = i - OFF_IN; }
    else if (i < OFF_HH)   { src = W_ih;   off = i - OFF_IH; }
    else if (i < OFF_POST) { src = W_hh;   off = i - OFF_HH; }
    else                   { src = W_post; off = i - OFF_POST; }
    float4 v = *reinterpret_cast<const float4*>(src + off);
    float4 h, l;
    h.x = tf32_rna(v.x); l.x = tf32_rna(v.x - h.x);
    h.y = tf32_rna(v.y); l.y = tf32_rna(v.y - h.y);
    h.z = tf32_rna(v.z); l.z = tf32_rna(v.z - h.z);
    h.w = tf32_rna(v.w); l.w = tf32_rna(v.w - h.w);
    *reinterpret_cast<float4*>(g_wh + i) = h;
    *reinterpret_cast<float4*>(g_wl + i) = l;
}

// ---------------- 3xTF32 mma.sync GEMM (main path) ----------------
#define LSTR 36
#define STAGE_F (4 * 128 * LSTR)
#define SMEM_MMA (2 * STAGE_F * 4)

__device__ __forceinline__ void mma8(float c[4], const uint32_t a[4], const uint32_t b[2]) {
    asm volatile("mma.sync.aligned.m16n8k8.row.col.f32.tf32.tf32.f32 "
                 "{%0,%1,%2,%3}, {%4,%5,%6,%7}, {%8,%9}, {%0,%1,%2,%3};"
                 : "+f"(c[0]), "+f"(c[1]), "+f"(c[2]), "+f"(c[3])
                 : "r"(a[0]), "r"(a[1]), "r"(a[2]), "r"(a[3]), "r"(b[0]), "r"(b[1]));
}

__global__ __launch_bounds__(256, 1)
void mma_gemm(const float* __restrict__ A1, int K1,
              const float* __restrict__ A2, int K2,
              const unsigned char* __restrict__ mask,
              const float* __restrict__ Bh,
              const float* __restrict__ Bl,
              const float* __restrict__ bias,
              float* __restrict__ C, int Ntot)
{
    extern __shared__ __align__(16) float sm[];
    const int K  = K1 + K2;
    const int KC = K >> 5;
    const int bm = blockIdx.y << 7;
    const int bn = blockIdx.x << 7;
    const int t  = threadIdx.x;
    const int wid  = t >> 5;
    const int lane = t & 31;
    const int g = lane >> 2;
    const int c = lane & 3;
    const int wm = (wid >> 2) << 6;
    const int wn = (wid & 3) << 5;

    float acc[4][4][4];
#pragma unroll
    for (int i = 0; i < 4; i++)
#pragma unroll
        for (int j = 0; j < 4; j++)
#pragma unroll
            for (int r = 0; r < 4; r++) acc[i][j][r] = 0.f;

    float4 ar[4], brh[4], brl[4];

    auto ldg = [&](int kc) {
        const int kt = kc << 5;
#pragma unroll
        for (int i = 0; i < 4; i++) {
            int f = t + (i << 8);
            int row = f >> 3, kq = (f & 7) << 2;
            int kg = kt + kq;
            int m  = bm + row;
            float4 v;
            if (kg < K1) {
                if (mask != nullptr && mask[m]) v = make_float4(0.f, 0.f, 0.f, 0.f);
                else v = *reinterpret_cast<const float4*>(A1 + (size_t)m * K1 + kg);
            } else {
                v = *reinterpret_cast<const float4*>(A2 + (size_t)m * K2 + (kg - K1));
            }
            ar[i] = v;
            size_t boff = (size_t)(bn + row) * K + kg;
            brh[i] = *reinterpret_cast<const float4*>(Bh + boff);
            brl[i] = *reinterpret_cast<const float4*>(Bl + boff);
        }
    };

    auto sts = [&](int buf) {
        float* S = sm + buf * STAGE_F;
#pragma unroll
        for (int i = 0; i < 4; i++) {
            int f = t + (i << 8);
            int row = f >> 3, kq = (f & 7) << 2;
            int o = row * LSTR + kq;
            float4 v = ar[i];
            float hx = tf32_rna(v.x), hy = tf32_rna(v.y);
            float hz = tf32_rna(v.z), hw = tf32_rna(v.w);
            *reinterpret_cast<float4*>(S + o) = make_float4(hx, hy, hz, hw);
            *reinterpret_cast<float4*>(S + 128 * LSTR + o) =
                make_float4(tf32_rna(v.x - hx), tf32_rna(v.y - hy),
                            tf32_rna(v.z - hz), tf32_rna(v.w - hw));
            *reinterpret_cast<float4*>(S + 2 * 128 * LSTR + o) = brh[i];
            *reinterpret_cast<float4*>(S + 3 * 128 * LSTR + o) = brl[i];
        }
    };

    ldg(0); sts(0);
    __syncthreads();
    ldg(1);

    for (int k = 0; k < KC; k++) {
        if (k + 1 < KC) sts((k + 1) & 1);

        const float* S   = sm + (k & 1) * STAGE_F;
        const float* pAh = S;
        const float* pAl = S + 128 * LSTR;
        const float* pBh = S + 2 * 128 * LSTR;
        const float* pBl = S + 3 * 128 * LSTR;

#pragma unroll
        for (int ks = 0; ks < 4; ks++) {
            const int k8 = ks << 3;
            uint32_t aH[4][4], aL[4][4], bH[4][2], bL[4][2];
#pragma unroll
            for (int i = 0; i < 4; i++) {
                int r0 = (wm + (i << 4) + g) * LSTR + k8 + c;
                aH[i][0] = __float_as_uint(pAh[r0]);
                aH[i][1] = __float_as_uint(pAh[r0 + 8 * LSTR]);
                aH[i][2] = __float_as_uint(pAh[r0 + 4]);
                aH[i][3] = __float_as_uint(pAh[r0 + 8 * LSTR + 4]);
                aL[i][0] = __float_as_uint(pAl[r0]);
                aL[i][1] = __float_as_uint(pAl[r0 + 8 * LSTR]);
                aL[i][2] = __float_as_uint(pAl[r0 + 4]);
                aL[i][3] = __float_as_uint(pAl[r0 + 8 * LSTR + 4]);
            }
#pragma unroll
            for (int j = 0; j < 4; j++) {
                int r0 = (wn + (j << 3) + g) * LSTR + k8 + c;
                bH[j][0] = __float_as_uint(pBh[r0]);
                bH[j][1] = __float_as_uint(pBh[r0 + 4]);
                bL[j][0] = __float_as_uint(pBl[r0]);
                bL[j][1] = __float_as_uint(pBl[r0 + 4]);
            }
#pragma unroll
            for (int i = 0; i < 4; i++)
#pragma unroll
                for (int j = 0; j < 4; j++) mma8(acc[i][j], aH[i], bH[j]);
#pragma unroll
            for (int i = 0; i < 4; i++)
#pragma unroll
                for (int j = 0; j < 4; j++) mma8(acc[i][j], aL[i], bH[j]);
#pragma unroll
            for (int i = 0; i < 4; i++)
#pragma unroll
                for (int j = 0; j < 4; j++) mma8(acc[i][j], aH[i], bL[j]);
        }
        if (k + 2 < KC) ldg(k + 2);
        __syncthreads();
    }

#pragma unroll
    for (int i = 0; i < 4; i++) {
        int row0 = bm + wm + (i << 4) + g;
        int row1 = row0 + 8;
#pragma unroll
        for (int j = 0; j < 4; j++) {
            int col = bn + wn + (j << 3) + (c << 1);
            float2 b2 = *reinterpret_cast<const float2*>(bias + col);
            float2 v0 = make_float2(acc[i][j][0] + b2.x, acc[i][j][1] + b2.y);
            float2 v1 = make_float2(acc[i][j][2] + b2.x, acc[i][j][3] + b2.y);
            *reinterpret_cast<float2*>(C + (size_t)row0 * Ntot + col) = v0;
            *reinterpret_cast<float2*>(C + (size_t)row1 * Ntot + col) = v1;
        }
    }
}

// ---------------- fp32 FFMA GEMM (fix path, round-1 proven numerics) ----------------
#define GBM 128
#define GBN 128
#define GBK 16
#define GTM 8
#define GTN 8

__global__ __launch_bounds__(256, 2)
void gemm_f32(const float* __restrict__ A1, int K1,
              const float* __restrict__ A2, int K2,
              const float* __restrict__ B,
              const float* __restrict__ bias,
              float* __restrict__ C, int N)
{
    __shared__ __align__(16) float As[GBK][GBM];
    __shared__ __align__(16) float Bs[GBK][GBN];
    const int K  = K1 + K2;
    const int bm = blockIdx.y * GBM;
    const int bn = blockIdx.x * GBN;
    const int t  = threadIdx.x;
    const int tx = t & 15;
    const int ty = t >> 4;

    float acc[GTM][GTN];
#pragma unroll
    for (int i = 0; i < GTM; i++)
#pragma unroll
        for (int j = 0; j < GTN; j++) acc[i][j] = 0.f;

    for (int kt = 0; kt < K; kt += GBK) {
#pragma unroll
        for (int q = 0; q < 2; q++) {
            int li  = t * 2 + q;
            int row = li >> 2;
            int kq  = (li & 3) << 2;
            int kg  = kt + kq;
            {
                int m = bm + row;
                float4 v;
                if (kg < K1) v = *reinterpret_cast<const float4*>(A1 + (size_t)m * K1 + kg);
                else         v = *reinterpret_cast<const float4*>(A2 + (size_t)m * K2 + (kg - K1));
                As[kq + 0][row] = v.x; As[kq + 1][row] = v.y;
                As[kq + 2][row] = v.z; As[kq + 3][row] = v.w;
            }
            {
                int n = bn + row;
                float4 w = *reinterpret_cast<const float4*>(B + (size_t)n * K + kg);
                Bs[kq + 0][row] = w.x; Bs[kq + 1][row] = w.y;
                Bs[kq + 2][row] = w.z; Bs[kq + 3][row] = w.w;
            }
        }
        __syncthreads();
#pragma unroll
        for (int k = 0; k < GBK; k++) {
            float4 a0 = *reinterpret_cast<const float4*>(&As[k][ty * GTM]);
            float4 a1 = *reinterpret_cast<const float4*>(&As[k][ty * GTM + 4]);
            float4 b0 = *reinterpret_cast<const float4*>(&Bs[k][tx * GTN]);
            float4 b1 = *reinterpret_cast<const float4*>(&Bs[k][tx * GTN + 4]);
            float a[8] = {a0.x, a0.y, a0.z, a0.w, a1.x, a1.y, a1.z, a1.w};
            float b[8] = {b0.x, b0.y, b0.z, b0.w, b1.x, b1.y, b1.z, b1.w};
#pragma unroll
            for (int i = 0; i < GTM; i++)
#pragma unroll
                for (int j = 0; j < GTN; j++)
                    acc[i][j] = fmaf(a[i], b[j], acc[i][j]);
        }
        __syncthreads();
    }
#pragma unroll
    for (int i = 0; i < GTM; i++) {
        int m = bm + ty * GTM + i;
        float* crow = C + (size_t)m * N + bn + tx * GTN;
#pragma unroll
        for (int j = 0; j < GTN; j++)
            crow[j] = acc[i][j] + bias[bn + tx * GTN + j];
    }
}

// ---------------- GRU elementwise combine (main) ----------------
__global__ void gru_kernel(const float* __restrict__ deter,
                           const unsigned char* __restrict__ first,
                           float* __restrict__ h_out)
{
    int i = blockIdx.x * blockDim.x + threadIdx.x;
    if (i >= BSZ * REC) return;
    int m = i >> 10;
    int n = i & 1023;
    size_t base = (size_t)m * (3 * REC) + n;
    float ir  = g_gi[base];
    float iz  = g_gi[base + REC];
    float i_n = g_gi[base + 2 * REC];
    float hr  = g_gh[base];
    float hz  = g_gh[base + REC];
    float h_n = g_gh[base + 2 * REC];
    float d = first[m] ? 0.f : deter[i];
    float r  = 1.f / (1.f + expf(-(ir + hr)));
    float z  = 1.f / (1.f + expf(-(iz + hz)));
    float nn = tanhf(i_n + r * h_n);
    h_out[i] = (1.f - z) * nn + z * d;
}

// ---------------- threefry2x32 + gumbel ----------------
__device__ __forceinline__ uint32_t threefry_bits(uint32_t x1in)
{
    const uint32_t ks0 = 0u;
    const uint32_t ks1 = 42u;
    const uint32_t ks2 = 0x1BD11BDAu ^ ks0 ^ ks1;
    uint32_t x0 = 0u + ks0;
    uint32_t x1 = x1in + ks1;
#define TF_R(r) { x0 += x1; x1 = __funnelshift_l(x1, x1, (r)); x1 ^= x0; }
    TF_R(13) TF_R(15) TF_R(26) TF_R(6)
    x0 += ks1; x1 += ks2 + 1u;
    TF_R(17) TF_R(29) TF_R(16) TF_R(24)
    x0 += ks2; x1 += ks0 + 2u;
    TF_R(13) TF_R(15) TF_R(26) TF_R(6)
    x0 += ks0; x1 += ks1 + 3u;
    TF_R(17) TF_R(29) TF_R(16) TF_R(24)
    x0 += ks1; x1 += ks2 + 4u;
    TF_R(13) TF_R(15) TF_R(26) TF_R(6)
    x0 += ks2; x1 += ks0 + 5u;
#undef TF_R
    return x0 ^ x1;
}

__device__ __forceinline__ float gumbel_at(uint32_t idx)
{
    uint32_t bits = threefry_bits(idx);
    float f = __uint_as_float((bits >> 9) | 0x3f800000u) - 1.0f;
    float u = fmaxf(f, 1.17549435e-38f);
    float inner = -logf(u);
    return -__logf(inner);
}

// main sampler: writes one-hot, records ambiguous (near-tie) groups
__global__ void sample_kernel(const float* __restrict__ logits,
                              float* __restrict__ stoch_out)
{
    int g = blockIdx.x * blockDim.x + threadIdx.x;
    if (g >= BSZ * 32) return;
    const float4* lrow = reinterpret_cast<const float4*>(logits + (size_t)g * 32);
    float best = -3.4e38f, second = -3.4e38f;
    int   bi   = 0;
    uint32_t base = (uint32_t)g * 32u;
#pragma unroll
    for (int q = 0; q < 8; q++) {
        float4 lv = lrow[q];
        float l4[4] = {lv.x, lv.y, lv.z, lv.w};
#pragma unroll
        for (int ci = 0; ci < 4; ci++) {
            int d = q * 4 + ci;
            float s = l4[ci] + gumbel_at(base + (uint32_t)d);
            if (s > best) { second = best; best = s; bi = d; }
            else if (s > second) second = s;
        }
    }
    float4* dst = reinterpret_cast<float4*>(stoch_out + (size_t)g * 32);
#pragma unroll
    for (int q = 0; q < 8; q++) {
        float4 v;
        v.x = (bi == q * 4 + 0) ? 1.f : 0.f;
        v.y = (bi == q * 4 + 1) ? 1.f : 0.f;
        v.z = (bi == q * 4 + 2) ? 1.f : 0.f;
        v.w = (bi == q * 4 + 3) ? 1.f : 0.f;
        dst[q] = v;
    }
    if (best - second < FIX_TAU) {
        int slot = atomicAdd(&g_namb, 1);
        if (slot < AMB_CAP) g_amb[slot] = g;
    }
}

// ---------------- fix path ----------------
__global__ void init_fix()
{
    int t = blockIdx.x * blockDim.x + threadIdx.x;
    if (t == 0) { g_namb = 0; g_nrows = 0; }
    for (int i = t; i < BSZ; i += gridDim.x * blockDim.x) g_rowflag[i] = 0;
}

__global__ void gather_rows(const float* __restrict__ stoch,
                            const float* __restrict__ deter,
                            const float* __restrict__ action,
                            const float* __restrict__ obs,
                            const unsigned char* __restrict__ first)
{
    __shared__ int s_row, s_slot;
    int namb = min(g_namb, AMB_CAP);
    for (int e = blockIdx.x; e < namb; e += gridDim.x) {
        if (threadIdx.x == 0) {
            int row = g_amb[e] >> 5;
            int slot = -1;
            if (atomicExch(&g_rowflag[row], 1) == 0) {
                int s = atomicAdd(&g_nrows, 1);
                if (s < FIX_ROWS) { g_rowlist[s] = row; slot = s; }
            }
            s_row = row; s_slot = slot;
        }
        __syncthreads();
        int slot = s_slot, row = s_row;
        if (slot >= 0) {
            bool f = first[row] != 0;
            for (int j = threadIdx.x; j < SDIM; j += blockDim.x)
                g_fin[(size_t)slot * 1088 + j] = f ? 0.f : stoch[(size_t)row * SDIM + j];
            for (int j = threadIdx.x; j < ADIM; j += blockDim.x)
                g_fin[(size_t)slot * 1088 + SDIM + j] = action[(size_t)row * ADIM + j];
            for (int j = threadIdx.x; j < REC; j += blockDim.x)
                g_fdet[(size_t)slot * 1024 + j] = f ? 0.f : deter[(size_t)row * REC + j];
            for (int j = threadIdx.x; j < HID; j += blockDim.x)
                g_fobs[(size_t)slot * 1024 + j] = obs[(size_t)row * HID + j];
        }
        __syncthreads();
    }
}

__global__ void fgru_kernel()
{
    int i = blockIdx.x * blockDim.x + threadIdx.x;
    if (i >= FIX_ROWS * 1024) return;
    int r = i >> 10, n = i & 1023;
    size_t base = (size_t)r * 3072 + n;
    float ir  = g_fgi[base];
    float iz  = g_fgi[base + 1024];
    float i_n = g_fgi[base + 2048];
    float hr  = g_fgh[base];
    float hz  = g_fgh[base + 1024];
    float h_n = g_fgh[base + 2048];
    float d = g_fdet[i];                       // already reset-masked at gather
    float rr = 1.f / (1.f + expf(-(ir + hr)));
    float zz = 1.f / (1.f + expf(-(iz + hz)));
    float nn = tanhf(i_n + rr * h_n);
    g_fh[i] = (1.f - zz) * nn + zz * d;
}

// re-decide all 32 groups of each fixed row from fp32-accurate logits
__global__ void fix_sample(float* __restrict__ stoch_out)
{
    int idx = blockIdx.x * blockDim.x + threadIdx.x;
    int r = idx >> 5, gl = idx & 31;
    if (r >= min(g_nrows, FIX_ROWS)) return;
    int row = g_rowlist[r];
    const float* l = g_flog + (size_t)r * 1024 + gl * 32;
    uint32_t base = ((uint32_t)row * 32u + (uint32_t)gl) * 32u;
    float best = -3.4e38f;
    int bi = 0;
#pragma unroll
    for (int d = 0; d < 32; d++) {
        float s = l[d] + gumbel_at(base + (uint32_t)d);
        if (s > best) { best = s; bi = d; }
    }
    float* dst = stoch_out + (size_t)row * 1024 + gl * 32;
#pragma unroll
    for (int d = 0; d < 32; d++) dst[d] = (d == bi) ? 1.f : 0.f;
}

// ---------------- launch ----------------
extern "C" void kernel_launch(void* const* d_in, const int* in_sizes, int n_in,
                              void* d_out, int out_size)
{
    (void)in_sizes; (void)n_in; (void)out_size;
    const float* stoch  = (const float*)d_in[0];
    const float* deter  = (const float*)d_in[1];
    const float* action = (const float*)d_in[3];
    const float* obs    = (const float*)d_in[4];
    const unsigned char* first = (const unsigned char*)d_in[5];
    const float* W_in   = (const float*)d_in[6];
    const float* b_in   = (const float*)d_in[7];
    const float* W_ih   = (const float*)d_in[8];
    const float* b_ih   = (const float*)d_in[9];
    const float* W_hh   = (const float*)d_in[10];
    const float* b_hh   = (const float*)d_in[11];
    const float* W_post = (const float*)d_in[14];
    const float* b_post = (const float*)d_in[15];

    float* out        = (float*)d_out;
    float* h_out      = out;
    float* stoch_out  = out + (size_t)BSZ * LATD;
    float* logits_out = out + 2 * (size_t)BSZ * LATD;

    float *xp, *gip, *ghp, *wh, *wl;
    float *fin, *fdet, *fobs, *fx, *fgi, *fgh, *fh, *flog;
    cudaGetSymbolAddress((void**)&xp,  g_x);
    cudaGetSymbolAddress((void**)&gip, g_gi);
    cudaGetSymbolAddress((void**)&ghp, g_gh);
    cudaGetSymbolAddress((void**)&wh,  g_wh);
    cudaGetSymbolAddress((void**)&wl,  g_wl);
    cudaGetSymbolAddress((void**)&fin,  g_fin);
    cudaGetSymbolAddress((void**)&fdet, g_fdet);
    cudaGetSymbolAddress((void**)&fobs, g_fobs);
    cudaGetSymbolAddress((void**)&fx,   g_fx);
    cudaGetSymbolAddress((void**)&fgi,  g_fgi);
    cudaGetSymbolAddress((void**)&fgh,  g_fgh);
    cudaGetSymbolAddress((void**)&fh,   g_fh);
    cudaGetSymbolAddress((void**)&flog, g_flog);

    cudaFuncSetAttribute(mma_gemm, cudaFuncAttributeMaxDynamicSharedMemorySize, SMEM_MMA);

    dim3 thr(256);

    init_fix<<<64, 256>>>();
    split_w_kernel<<<(W_TOTAL / 4 + 255) / 256, 256>>>(W_in, W_ih, W_hh, W_post);

    // ---- main tf32-split path ----
    mma_gemm<<<dim3(HID / 128, BSZ / 128), thr, SMEM_MMA>>>(
        stoch, SDIM, action, ADIM, first,
        wh + OFF_IN, wl + OFF_IN, b_in, xp, HID);
    mma_gemm<<<dim3(3 * REC / 128, BSZ / 128), thr, SMEM_MMA>>>(
        xp, HID, xp, 0, nullptr,
        wh + OFF_IH, wl + OFF_IH, b_ih, gip, 3 * REC);
    mma_gemm<<<dim3(3 * REC / 128, BSZ / 128), thr, SMEM_MMA>>>(
        deter, REC, deter, 0, first,
        wh + OFF_HH, wl + OFF_HH, b_hh, ghp, 3 * REC);
    gru_kernel<<<(BSZ * REC) / 256, 256>>>(deter, first, h_out);
    mma_gemm<<<dim3(LATD / 128, BSZ / 128), thr, SMEM_MMA>>>(
        h_out, REC, obs, HID, nullptr,
        wh + OFF_POST, wl + OFF_POST, b_post, logits_out, LATD);
    sample_kernel<<<(BSZ * 32) / 256, 256>>>(logits_out, stoch_out);

    // ---- fp32 fix path for near-tie groups ----
    gather_rows<<<256, 256>>>(stoch, deter, action, obs, first);
    gemm_f32<<<dim3(HID / GBN, FIX_ROWS / GBM), thr>>>(
        fin, 1088, fin, 0, W_in, b_in, fx, HID);
    gemm_f32<<<dim3(3 * REC / GBN, FIX_ROWS / GBM), thr>>>(
        fx, 1024, fx, 0, W_ih, b_ih, fgi, 3 * REC);
    gemm_f32<<<dim3(3 * REC / GBN, FIX_ROWS / GBM), thr>>>(
        fdet, 1024, fdet, 0, W_hh, b_hh, fgh, 3 * REC);
    fgru_kernel<<<(FIX_ROWS * 1024) / 256, 256>>>();
    gemm_f32<<<dim3(LATD / GBN, FIX_ROWS / GBM), thr>>>(
        fh, 1024, fobs, 1024, W_post, b_post, flog, LATD);
    fix_sample<<<(FIX_ROWS * 32) / 256, 256>>>(stoch_out);
}

// round 6
// speedup vs baseline: 1.3021x; 1.1278x over previous
#include <cuda_runtime.h>
#include <cstdint>
#include <cstddef>

#define BSZ  16384
#define SDIM 1024
#define ADIM 64
#define HID  1024
#define REC  1024
#define LATD 1024

// Scratch
__device__ float g_x [(size_t)BSZ * HID];
__device__ float g_gi[(size_t)BSZ * 3 * REC];
__device__ float g_gh[(size_t)BSZ * 3 * REC];

// ---- ambiguous-group fix machinery ----
#define FIX_TAU  2e-4f
#define AMB_CAP  16384
#define FIX_ROWS 384
__device__ int   g_namb;
__device__ int   g_nrows;
__device__ int   g_amb[AMB_CAP];
__device__ int   g_rowlist[FIX_ROWS];
__device__ int   g_rowflag[BSZ];
__device__ float g_fin [(size_t)FIX_ROWS * 1088];
__device__ float g_fdet[(size_t)FIX_ROWS * 1024];
__device__ float g_fobs[(size_t)FIX_ROWS * 1024];
__device__ float g_fx  [(size_t)FIX_ROWS * 1024];
__device__ float g_fgi [(size_t)FIX_ROWS * 3072];
__device__ float g_fgh [(size_t)FIX_ROWS * 3072];
__device__ float g_fh  [(size_t)FIX_ROWS * 1024];
__device__ float g_flog[(size_t)FIX_ROWS * 1024];

__device__ __forceinline__ float tf32_rna(float a) {
    uint32_t u;
    asm("cvt.rna.tf32.f32 %0, %1;" : "=r"(u) : "f"(a));
    return __uint_as_float(u);
}
__device__ __forceinline__ uint32_t smem_u32(const void* p) {
    uint32_t a;
    asm("{ .reg .u64 t; cvta.to.shared.u64 t, %1; cvt.u32.u64 %0, t; }"
        : "=r"(a) : "l"(p));
    return a;
}
__device__ __forceinline__ void cp16(uint32_t dst, const void* src, uint32_t sz) {
    asm volatile("cp.async.cg.shared.global [%0], [%1], 16, %2;"
                 :: "r"(dst), "l"(src), "r"(sz) : "memory");
}
#define CP_COMMIT() asm volatile("cp.async.commit_group;" ::: "memory")
#define CP_WAIT(n)  asm volatile("cp.async.wait_group %0;" :: "n"(n) : "memory")

// ---------------- 3xTF32 mma.sync GEMM, cp.async multistage ----------------
// C[m,n] = bias[n] + sum_k Acat[m,k]*B[n,k]
// Acat=[A1(per-row zero via cp.async src-size)|A2], B raw NxK row-major.
// CTA 128x128 tile, 256 thr (8 warps 2x4), warp tile 64x32.
// K-chunk 32, 3-stage raw-f32 smem ring (stride 36 floats), split at consume.
#define RSTR 36
#define STG_W   (128 * RSTR)                  // words per A (or B) tile
#define STG_BYTES (2 * STG_W * 4)             // 36864 per stage
#define NSTAGE 3
#define SMEM_CA (NSTAGE * STG_BYTES)          // 110592

__device__ __forceinline__ void mma8(float c[4], const uint32_t a[4], const uint32_t b[2]) {
    asm volatile("mma.sync.aligned.m16n8k8.row.col.f32.tf32.tf32.f32 "
                 "{%0,%1,%2,%3}, {%4,%5,%6,%7}, {%8,%9}, {%0,%1,%2,%3};"
                 : "+f"(c[0]), "+f"(c[1]), "+f"(c[2]), "+f"(c[3])
                 : "r"(a[0]), "r"(a[1]), "r"(a[2]), "r"(a[3]), "r"(b[0]), "r"(b[1]));
}
__device__ __forceinline__ void split2(float x, uint32_t& hi, uint32_t& lo) {
    float h = tf32_rna(x);
    hi = __float_as_uint(h);
    lo = __float_as_uint(tf32_rna(x - h));
}

__global__ __launch_bounds__(256, 1)
void mma_gemm(const float* __restrict__ A1, int K1,
              const float* __restrict__ A2, int K2,
              const unsigned char* __restrict__ mask,
              const float* __restrict__ B,
              const float* __restrict__ bias,
              float* __restrict__ C, int Ntot)
{
    extern __shared__ __align__(16) float sm[];
    const uint32_t sbase = smem_u32(sm);

    const int K  = K1 + K2;
    const int KC = K >> 5;
    const int bm = blockIdx.y << 7;
    const int bn = blockIdx.x << 7;
    const int t  = threadIdx.x;
    const int wid  = t >> 5;
    const int lane = t & 31;
    const int g = lane >> 2;
    const int c = lane & 3;
    const int wm = (wid >> 2) << 6;
    const int wn = (wid & 3) << 5;

    // per-thread fixed rows for the copy phase
    int rowA[4];
    uint32_t msz[4];
#pragma unroll
    for (int i = 0; i < 4; i++) {
        rowA[i] = (t + (i << 8)) >> 3;
        msz[i] = (mask != nullptr && mask[bm + rowA[i]]) ? 0u : 16u;
    }

    auto issue_stage = [&](int kc) {
        if (kc < KC) {
            const int kt = kc << 5;
            const uint32_t st = sbase + (uint32_t)(kc % NSTAGE) * STG_BYTES;
#pragma unroll
            for (int i = 0; i < 4; i++) {
                int f = t + (i << 8);
                int row = f >> 3, kq = (f & 7) << 2;
                int kg = kt + kq;
                uint32_t dA = st + (uint32_t)(row * RSTR + kq) * 4u;
                if (kg < K1)
                    cp16(dA, A1 + (size_t)(bm + row) * K1 + kg, msz[i]);
                else
                    cp16(dA, A2 + (size_t)(bm + row) * K2 + (kg - K1), 16u);
                uint32_t dB = st + (uint32_t)(STG_W + row * RSTR + kq) * 4u;
                cp16(dB, B + (size_t)(bn + row) * K + kg, 16u);
            }
        }
        CP_COMMIT();
    };

    float acc[4][4][4];
#pragma unroll
    for (int i = 0; i < 4; i++)
#pragma unroll
        for (int j = 0; j < 4; j++)
#pragma unroll
            for (int r = 0; r < 4; r++) acc[i][j][r] = 0.f;

    issue_stage(0);
    issue_stage(1);

    for (int k = 0; k < KC; k++) {
        CP_WAIT(1);
        __syncthreads();
        issue_stage(k + 2);

        const float* SA = sm + (size_t)(k % NSTAGE) * (2 * STG_W);
        const float* SB = SA + STG_W;

#pragma unroll
        for (int ks = 0; ks < 4; ks++) {
            const int k8 = ks << 3;
            uint32_t aH[4][4], aL[4][4], bH[4][2], bL[4][2];
#pragma unroll
            for (int i = 0; i < 4; i++) {
                int r0 = (wm + (i << 4) + g) * RSTR + k8 + c;
                split2(SA[r0],                aH[i][0], aL[i][0]);
                split2(SA[r0 + 8 * RSTR],     aH[i][1], aL[i][1]);
                split2(SA[r0 + 4],            aH[i][2], aL[i][2]);
                split2(SA[r0 + 8 * RSTR + 4], aH[i][3], aL[i][3]);
            }
#pragma unroll
            for (int j = 0; j < 4; j++) {
                int r0 = (wn + (j << 3) + g) * RSTR + k8 + c;
                split2(SB[r0],     bH[j][0], bL[j][0]);
                split2(SB[r0 + 4], bH[j][1], bL[j][1]);
            }
#pragma unroll
            for (int i = 0; i < 4; i++)
#pragma unroll
                for (int j = 0; j < 4; j++) mma8(acc[i][j], aH[i], bH[j]);
#pragma unroll
            for (int i = 0; i < 4; i++)
#pragma unroll
                for (int j = 0; j < 4; j++) mma8(acc[i][j], aL[i], bH[j]);
#pragma unroll
            for (int i = 0; i < 4; i++)
#pragma unroll
                for (int j = 0; j < 4; j++) mma8(acc[i][j], aH[i], bL[j]);
        }
        __syncthreads();
    }

#pragma unroll
    for (int i = 0; i < 4; i++) {
        int row0 = bm + wm + (i << 4) + g;
        int row1 = row0 + 8;
#pragma unroll
        for (int j = 0; j < 4; j++) {
            int col = bn + wn + (j << 3) + (c << 1);
            float2 b2 = *reinterpret_cast<const float2*>(bias + col);
            float2 v0 = make_float2(acc[i][j][0] + b2.x, acc[i][j][1] + b2.y);
            float2 v1 = make_float2(acc[i][j][2] + b2.x, acc[i][j][3] + b2.y);
            *reinterpret_cast<float2*>(C + (size_t)row0 * Ntot + col) = v0;
            *reinterpret_cast<float2*>(C + (size_t)row1 * Ntot + col) = v1;
        }
    }
}

// ---------------- fp32 FFMA GEMM (fix path) ----------------
#define GBM 128
#define GBN 128
#define GBK 16
#define GTM 8
#define GTN 8

__global__ __launch_bounds__(256, 2)
void gemm_f32(const float* __restrict__ A1, int K1,
              const float* __restrict__ A2, int K2,
              const float* __restrict__ B,
              const float* __restrict__ bias,
              float* __restrict__ C, int N)
{
    __shared__ __align__(16) float As[GBK][GBM];
    __shared__ __align__(16) float Bs[GBK][GBN];
    const int K  = K1 + K2;
    const int bm = blockIdx.y * GBM;
    const int bn = blockIdx.x * GBN;
    const int t  = threadIdx.x;
    const int tx = t & 15;
    const int ty = t >> 4;

    float acc[GTM][GTN];
#pragma unroll
    for (int i = 0; i < GTM; i++)
#pragma unroll
        for (int j = 0; j < GTN; j++) acc[i][j] = 0.f;

    for (int kt = 0; kt < K; kt += GBK) {
#pragma unroll
        for (int q = 0; q < 2; q++) {
            int li  = t * 2 + q;
            int row = li >> 2;
            int kq  = (li & 3) << 2;
            int kg  = kt + kq;
            {
                int m = bm + row;
                float4 v;
                if (kg < K1) v = *reinterpret_cast<const float4*>(A1 + (size_t)m * K1 + kg);
                else         v = *reinterpret_cast<const float4*>(A2 + (size_t)m * K2 + (kg - K1));
                As[kq + 0][row] = v.x; As[kq + 1][row] = v.y;
                As[kq + 2][row] = v.z; As[kq + 3][row] = v.w;
            }
            {
                int n = bn + row;
                float4 w = *reinterpret_cast<const float4*>(B + (size_t)n * K + kg);
                Bs[kq + 0][row] = w.x; Bs[kq + 1][row] = w.y;
                Bs[kq + 2][row] = w.z; Bs[kq + 3][row] = w.w;
            }
        }
        __syncthreads();
#pragma unroll
        for (int k = 0; k < GBK; k++) {
            float4 a0 = *reinterpret_cast<const float4*>(&As[k][ty * GTM]);
            float4 a1 = *reinterpret_cast<const float4*>(&As[k][ty * GTM + 4]);
            float4 b0 = *reinterpret_cast<const float4*>(&Bs[k][tx * GTN]);
            float4 b1 = *reinterpret_cast<const float4*>(&Bs[k][tx * GTN + 4]);
            float a[8] = {a0.x, a0.y, a0.z, a0.w, a1.x, a1.y, a1.z, a1.w};
            float b[8] = {b0.x, b0.y, b0.z, b0.w, b1.x, b1.y, b1.z, b1.w};
#pragma unroll
            for (int i = 0; i < GTM; i++)
#pragma unroll
                for (int j = 0; j < GTN; j++)
                    acc[i][j] = fmaf(a[i], b[j], acc[i][j]);
        }
        __syncthreads();
    }
#pragma unroll
    for (int i = 0; i < GTM; i++) {
        int m = bm + ty * GTM + i;
        float* crow = C + (size_t)m * N + bn + tx * GTN;
#pragma unroll
        for (int j = 0; j < GTN; j++)
            crow[j] = acc[i][j] + bias[bn + tx * GTN + j];
    }
}

// ---------------- GRU elementwise combine ----------------
__global__ void gru_kernel(const float* __restrict__ deter,
                           const unsigned char* __restrict__ first,
                           float* __restrict__ h_out)
{
    int i = blockIdx.x * blockDim.x + threadIdx.x;
    if (i >= BSZ * REC) return;
    int m = i >> 10;
    int n = i & 1023;
    size_t base = (size_t)m * (3 * REC) + n;
    float ir  = g_gi[base];
    float iz  = g_gi[base + REC];
    float i_n = g_gi[base + 2 * REC];
    float hr  = g_gh[base];
    float hz  = g_gh[base + REC];
    float h_n = g_gh[base + 2 * REC];
    float d = first[m] ? 0.f : deter[i];
    float r  = 1.f / (1.f + expf(-(ir + hr)));
    float z  = 1.f / (1.f + expf(-(iz + hz)));
    float nn = tanhf(i_n + r * h_n);
    h_out[i] = (1.f - z) * nn + z * d;
}

// ---------------- threefry2x32 + gumbel ----------------
__device__ __forceinline__ uint32_t threefry_bits(uint32_t x1in)
{
    const uint32_t ks0 = 0u;
    const uint32_t ks1 = 42u;
    const uint32_t ks2 = 0x1BD11BDAu ^ ks0 ^ ks1;
    uint32_t x0 = 0u + ks0;
    uint32_t x1 = x1in + ks1;
#define TF_R(r) { x0 += x1; x1 = __funnelshift_l(x1, x1, (r)); x1 ^= x0; }
    TF_R(13) TF_R(15) TF_R(26) TF_R(6)
    x0 += ks1; x1 += ks2 + 1u;
    TF_R(17) TF_R(29) TF_R(16) TF_R(24)
    x0 += ks2; x1 += ks0 + 2u;
    TF_R(13) TF_R(15) TF_R(26) TF_R(6)
    x0 += ks0; x1 += ks1 + 3u;
    TF_R(17) TF_R(29) TF_R(16) TF_R(24)
    x0 += ks1; x1 += ks2 + 4u;
    TF_R(13) TF_R(15) TF_R(26) TF_R(6)
    x0 += ks2; x1 += ks0 + 5u;
#undef TF_R
    return x0 ^ x1;
}

__device__ __forceinline__ float gumbel_at(uint32_t idx)
{
    uint32_t bits = threefry_bits(idx);
    float f = __uint_as_float((bits >> 9) | 0x3f800000u) - 1.0f;
    float u = fmaxf(f, 1.17549435e-38f);
    float inner = -logf(u);
    return -__logf(inner);
}

// main sampler: writes one-hot, records ambiguous (near-tie) groups
__global__ void sample_kernel(const float* __restrict__ logits,
                              float* __restrict__ stoch_out)
{
    int g = blockIdx.x * blockDim.x + threadIdx.x;
    if (g >= BSZ * 32) return;
    const float4* lrow = reinterpret_cast<const float4*>(logits + (size_t)g * 32);
    float best = -3.4e38f, second = -3.4e38f;
    int   bi   = 0;
    uint32_t base = (uint32_t)g * 32u;
#pragma unroll
    for (int q = 0; q < 8; q++) {
        float4 lv = lrow[q];
        float l4[4] = {lv.x, lv.y, lv.z, lv.w};
#pragma unroll
        for (int ci = 0; ci < 4; ci++) {
            int d = q * 4 + ci;
            float s = l4[ci] + gumbel_at(base + (uint32_t)d);
            if (s > best) { second = best; best = s; bi = d; }
            else if (s > second) second = s;
        }
    }
    float4* dst = reinterpret_cast<float4*>(stoch_out + (size_t)g * 32);
#pragma unroll
    for (int q = 0; q < 8; q++) {
        float4 v;
        v.x = (bi == q * 4 + 0) ? 1.f : 0.f;
        v.y = (bi == q * 4 + 1) ? 1.f : 0.f;
        v.z = (bi == q * 4 + 2) ? 1.f : 0.f;
        v.w = (bi == q * 4 + 3) ? 1.f : 0.f;
        dst[q] = v;
    }
    if (best - second < FIX_TAU) {
        int slot = atomicAdd(&g_namb, 1);
        if (slot < AMB_CAP) g_amb[slot] = g;
    }
}

// ---------------- fix path ----------------
__global__ void init_fix()
{
    int t = blockIdx.x * blockDim.x + threadIdx.x;
    if (t == 0) { g_namb = 0; g_nrows = 0; }
    for (int i = t; i < BSZ; i += gridDim.x * blockDim.x) g_rowflag[i] = 0;
}

__global__ void gather_rows(const float* __restrict__ stoch,
                            const float* __restrict__ deter,
                            const float* __restrict__ action,
                            const float* __restrict__ obs,
                            const unsigned char* __restrict__ first)
{
    __shared__ int s_row, s_slot;
    int namb = min(g_namb, AMB_CAP);
    for (int e = blockIdx.x; e < namb; e += gridDim.x) {
        if (threadIdx.x == 0) {
            int row = g_amb[e] >> 5;
            int slot = -1;
            if (atomicExch(&g_rowflag[row], 1) == 0) {
                int s = atomicAdd(&g_nrows, 1);
                if (s < FIX_ROWS) { g_rowlist[s] = row; slot = s; }
            }
            s_row = row; s_slot = slot;
        }
        __syncthreads();
        int slot = s_slot, row = s_row;
        if (slot >= 0) {
            bool f = first[row] != 0;
            for (int j = threadIdx.x; j < SDIM; j += blockDim.x)
                g_fin[(size_t)slot * 1088 + j] = f ? 0.f : stoch[(size_t)row * SDIM + j];
            for (int j = threadIdx.x; j < ADIM; j += blockDim.x)
                g_fin[(size_t)slot * 1088 + SDIM + j] = action[(size_t)row * ADIM + j];
            for (int j = threadIdx.x; j < REC; j += blockDim.x)
                g_fdet[(size_t)slot * 1024 + j] = f ? 0.f : deter[(size_t)row * REC + j];
            for (int j = threadIdx.x; j < HID; j += blockDim.x)
                g_fobs[(size_t)slot * 1024 + j] = obs[(size_t)row * HID + j];
        }
        __syncthreads();
    }
}

__global__ void fgru_kernel()
{
    int i = blockIdx.x * blockDim.x + threadIdx.x;
    if (i >= FIX_ROWS * 1024) return;
    int r = i >> 10, n = i & 1023;
    size_t base = (size_t)r * 3072 + n;
    float ir  = g_fgi[base];
    float iz  = g_fgi[base + 1024];
    float i_n = g_fgi[base + 2048];
    float hr  = g_fgh[base];
    float hz  = g_fgh[base + 1024];
    float h_n = g_fgh[base + 2048];
    float d = g_fdet[i];
    float rr = 1.f / (1.f + expf(-(ir + hr)));
    float zz = 1.f / (1.f + expf(-(iz + hz)));
    float nn = tanhf(i_n + rr * h_n);
    g_fh[i] = (1.f - zz) * nn + zz * d;
}

__global__ void fix_sample(float* __restrict__ stoch_out)
{
    int idx = blockIdx.x * blockDim.x + threadIdx.x;
    int r = idx >> 5, gl = idx & 31;
    if (r >= min(g_nrows, FIX_ROWS)) return;
    int row = g_rowlist[r];
    const float* l = g_flog + (size_t)r * 1024 + gl * 32;
    uint32_t base = ((uint32_t)row * 32u + (uint32_t)gl) * 32u;
    float best = -3.4e38f;
    int bi = 0;
#pragma unroll
    for (int d = 0; d < 32; d++) {
        float s = l[d] + gumbel_at(base + (uint32_t)d);
        if (s > best) { best = s; bi = d; }
    }
    float* dst = stoch_out + (size_t)row * 1024 + gl * 32;
#pragma unroll
    for (int d = 0; d < 32; d++) dst[d] = (d == bi) ? 1.f : 0.f;
}

// ---------------- launch ----------------
extern "C" void kernel_launch(void* const* d_in, const int* in_sizes, int n_in,
                              void* d_out, int out_size)
{
    (void)in_sizes; (void)n_in; (void)out_size;
    const float* stoch  = (const float*)d_in[0];
    const float* deter  = (const float*)d_in[1];
    const float* action = (const float*)d_in[3];
    const float* obs    = (const float*)d_in[4];
    const unsigned char* first = (const unsigned char*)d_in[5];
    const float* W_in   = (const float*)d_in[6];
    const float* b_in   = (const float*)d_in[7];
    const float* W_ih   = (const float*)d_in[8];
    const float* b_ih   = (const float*)d_in[9];
    const float* W_hh   = (const float*)d_in[10];
    const float* b_hh   = (const float*)d_in[11];
    const float* W_post = (const float*)d_in[14];
    const float* b_post = (const float*)d_in[15];

    float* out        = (float*)d_out;
    float* h_out      = out;
    float* stoch_out  = out + (size_t)BSZ * LATD;
    float* logits_out = out + 2 * (size_t)BSZ * LATD;

    float *xp, *gip, *ghp;
    float *fin, *fdet, *fobs, *fx, *fgi, *fgh, *fh, *flog;
    cudaGetSymbolAddress((void**)&xp,  g_x);
    cudaGetSymbolAddress((void**)&gip, g_gi);
    cudaGetSymbolAddress((void**)&ghp, g_gh);
    cudaGetSymbolAddress((void**)&fin,  g_fin);
    cudaGetSymbolAddress((void**)&fdet, g_fdet);
    cudaGetSymbolAddress((void**)&fobs, g_fobs);
    cudaGetSymbolAddress((void**)&fx,   g_fx);
    cudaGetSymbolAddress((void**)&fgi,  g_fgi);
    cudaGetSymbolAddress((void**)&fgh,  g_fgh);
    cudaGetSymbolAddress((void**)&fh,   g_fh);
    cudaGetSymbolAddress((void**)&flog, g_flog);

    cudaFuncSetAttribute(mma_gemm, cudaFuncAttributeMaxDynamicSharedMemorySize, SMEM_CA);

    dim3 thr(256);

    init_fix<<<64, 256>>>();

    // ---- main tf32-split path (raw weights, split at consume) ----
    mma_gemm<<<dim3(HID / 128, BSZ / 128), thr, SMEM_CA>>>(
        stoch, SDIM, action, ADIM, first, W_in, b_in, xp, HID);
    mma_gemm<<<dim3(3 * REC / 128, BSZ / 128), thr, SMEM_CA>>>(
        xp, HID, xp, 0, nullptr, W_ih, b_ih, gip, 3 * REC);
    mma_gemm<<<dim3(3 * REC / 128, BSZ / 128), thr, SMEM_CA>>>(
        deter, REC, deter, 0, first, W_hh, b_hh, ghp, 3 * REC);
    gru_kernel<<<(BSZ * REC) / 256, 256>>>(deter, first, h_out);
    mma_gemm<<<dim3(LATD / 128, BSZ / 128), thr, SMEM_CA>>>(
        h_out, REC, obs, HID, nullptr, W_post, b_post, logits_out, LATD);
    sample_kernel<<<(BSZ * 32) / 256, 256>>>(logits_out, stoch_out);

    // ---- fp32 fix path for near-tie groups ----
    gather_rows<<<256, 256>>>(stoch, deter, action, obs, first);
    gemm_f32<<<dim3(HID / GBN, FIX_ROWS / GBM), thr>>>(
        fin, 1088, fin, 0, W_in, b_in, fx, HID);
    gemm_f32<<<dim3(3 * REC / GBN, FIX_ROWS / GBM), thr>>>(
        fx, 1024, fx, 0, W_ih, b_ih, fgi, 3 * REC);
    gemm_f32<<<dim3(3 * REC / GBN, FIX_ROWS / GBM), thr>>>(
        fdet, 1024, fdet, 0, W_hh, b_hh, fgh, 3 * REC);
    fgru_kernel<<<(FIX_ROWS * 1024) / 256, 256>>>();
    gemm_f32<<<dim3(LATD / GBN, FIX_ROWS / GBM), thr>>>(
        fh, 1024, fobs, 1024, W_post, b_post, flog, LATD);
    fix_sample<<<(FIX_ROWS * 32) / 256, 256>>>(stoch_out);
}